// round 1
// baseline (speedup 1.0000x reference)
#include <cuda_runtime.h>
#include <math.h>

#define V_NUM 6890
#define B_NUM 512
#define J_NUM 24
#define KP    207   // (J-1)*9
#define NBETA 10
#define VC    (V_NUM*3)   // 20670

__constant__ int c_par[24] = {-1,0,0,0,1,2,3,4,5,6,7,8,9,9,9,12,13,14,16,17,18,19,20,21};

// Scratch (no allocations allowed)
__device__ float g_Jt0[J_NUM*3];
__device__ float g_JS[J_NUM*3*NBETA];
__device__ __align__(16) float g_pfT[KP*B_NUM];          // transposed pose_feature [k][b]
__device__ __align__(16) float g_A[B_NUM*J_NUM*12];      // per-batch joint affines (3x4)

// ---------------------------------------------------------------------------
// Kernel 1: batch-independent joint regressor folding:
//   Jt0[j][c] = sum_v Jreg[j][v] * vt[v][c]
//   JS[j][c][k] = sum_v Jreg[j][v] * shapedirs[v][c][k]
// ---------------------------------------------------------------------------
__global__ void regress_k(const float* __restrict__ Jreg,
                          const float* __restrict__ vt,
                          const float* __restrict__ sd)
{
    int j = blockIdx.x;
    int t = threadIdx.x;   // 128
    float acc[33];
#pragma unroll
    for (int i = 0; i < 33; i++) acc[i] = 0.f;
    for (int v = t; v < V_NUM; v += 128) {
        float r = Jreg[j*V_NUM + v];
#pragma unroll
        for (int c = 0; c < 3; c++) acc[c] += r * vt[v*3+c];
#pragma unroll
        for (int i = 0; i < 30; i++) acc[3+i] += r * sd[v*30+i];
    }
    __shared__ float red[128];
    for (int i = 0; i < 33; i++) {
        red[t] = acc[i];
        __syncthreads();
        for (int s = 64; s > 0; s >>= 1) {
            if (t < s) red[t] += red[t+s];
            __syncthreads();
        }
        if (t == 0) {
            if (i < 3) g_Jt0[j*3+i] = red[0];
            else       g_JS[j*30 + (i-3)] = red[0];
        }
        __syncthreads();
    }
}

// ---------------------------------------------------------------------------
// Kernel 2: per-batch (one warp per batch): Rodrigues, joints, kinematic
// chain, pose_feature (transposed), joint affines A.
// ---------------------------------------------------------------------------
__global__ void pose_k(const float* __restrict__ pose,
                       const float* __restrict__ betas)
{
    int b = blockIdx.x;
    int lane = threadIdx.x;   // 32
    __shared__ float R[24][9];
    __shared__ float Jt[24][3];
    __shared__ float Tl[24][12];
    __shared__ float Tw[24][12];

    if (lane < 24) {
        float rx = pose[b*72 + lane*3 + 0];
        float ry = pose[b*72 + lane*3 + 1];
        float rz = pose[b*72 + lane*3 + 2];
        float ang = sqrtf(rx*rx + ry*ry + rz*rz + 1e-16f);
        float inv = 1.0f/ang;
        float ax = rx*inv, ay = ry*inv, az = rz*inv;
        float s = sinf(ang), c = cosf(ang), tt = 1.0f - c;
        R[lane][0] = c + tt*ax*ax;    R[lane][1] = tt*ax*ay - s*az; R[lane][2] = tt*ax*az + s*ay;
        R[lane][3] = tt*ax*ay + s*az; R[lane][4] = c + tt*ay*ay;    R[lane][5] = tt*ay*az - s*ax;
        R[lane][6] = tt*ax*az - s*ay; R[lane][7] = tt*ay*az + s*ax; R[lane][8] = c + tt*az*az;

        float bet[NBETA];
#pragma unroll
        for (int k = 0; k < NBETA; k++) bet[k] = betas[b*NBETA + k];
#pragma unroll
        for (int c3 = 0; c3 < 3; c3++) {
            float a = g_Jt0[lane*3 + c3];
#pragma unroll
            for (int k = 0; k < NBETA; k++) a += g_JS[lane*30 + c3*10 + k] * bet[k];
            Jt[lane][c3] = a;
        }
    }
    __syncwarp();

    // pose_feature (rot[1:] - I), stored transposed [k][b]
    for (int idx = lane; idx < KP; idx += 32) {
        int j = idx/9 + 1, e = idx%9;
        float v = R[j][e] - ((e == 0 || e == 4 || e == 8) ? 1.0f : 0.0f);
        g_pfT[idx*B_NUM + b] = v;
    }

    // local transforms [R | rel_j]
    if (lane < 24) {
        float tx, ty, tz;
        if (lane == 0) { tx = Jt[0][0]; ty = Jt[0][1]; tz = Jt[0][2]; }
        else {
            int p = c_par[lane];
            tx = Jt[lane][0] - Jt[p][0];
            ty = Jt[lane][1] - Jt[p][1];
            tz = Jt[lane][2] - Jt[p][2];
        }
        Tl[lane][0] = R[lane][0]; Tl[lane][1] = R[lane][1]; Tl[lane][2]  = R[lane][2]; Tl[lane][3]  = tx;
        Tl[lane][4] = R[lane][3]; Tl[lane][5] = R[lane][4]; Tl[lane][6]  = R[lane][5]; Tl[lane][7]  = ty;
        Tl[lane][8] = R[lane][6]; Tl[lane][9] = R[lane][7]; Tl[lane][10] = R[lane][8]; Tl[lane][11] = tz;
    }
    __syncwarp();
    if (lane < 12) Tw[0][lane] = Tl[0][lane];
    __syncwarp();
    // kinematic chain (parents[i] < i)
    for (int i = 1; i < 24; i++) {
        if (lane < 12) {
            int r = lane >> 2, cc = lane & 3;
            int p = c_par[i];
            float v = Tw[p][r*4+0]*Tl[i][0+cc] + Tw[p][r*4+1]*Tl[i][4+cc] + Tw[p][r*4+2]*Tl[i][8+cc];
            if (cc == 3) v += Tw[p][r*4+3];
            Tw[i][lane] = v;
        }
        __syncwarp();
    }
    // A = [Rw | tw - Rw*J]
    if (lane < 24) {
        float jx = Jt[lane][0], jy = Jt[lane][1], jz = Jt[lane][2];
#pragma unroll
        for (int r = 0; r < 3; r++) {
            float r0 = Tw[lane][r*4+0], r1 = Tw[lane][r*4+1], r2 = Tw[lane][r*4+2];
            float t3 = Tw[lane][r*4+3] - (r0*jx + r1*jy + r2*jz);
            g_A[b*288 + lane*12 + r*4+0] = r0;
            g_A[b*288 + lane*12 + r*4+1] = r1;
            g_A[b*288 + lane*12 + r*4+2] = r2;
            g_A[b*288 + lane*12 + r*4+3] = t3;
        }
    }
}

// ---------------------------------------------------------------------------
// Kernel 3: main fused kernel.
// Block tile: 64 vertices x 32 batches, 256 threads.
// Thread tile: 4 consecutive vertices x 2 batches.
// Phase 1: v_posed = vt + shapedirs*betas + pose_feature @ posedirs  (K=207 GEMM)
// Phase 2: verts = sum_j w[v][j]*(A[b][j]*v_posed + t) + trans
// ---------------------------------------------------------------------------
__global__ void __launch_bounds__(256, 2) lbs_k(
    const float* __restrict__ trans,
    const float* __restrict__ vt,
    const float* __restrict__ sd,
    const float* __restrict__ pdirs,
    const float* __restrict__ wts,
    const float* __restrict__ betas,
    float* __restrict__ out)
{
    __shared__ __align__(16) float sA[32*288];   // phase2: A tile; phase1: overlaid pd/pf tiles
    __shared__ float sW[64*25];
    __shared__ float sB[32*NBETA];

    int t = threadIdx.x;
    int vg = t & 15;        // vertex group (4 verts each)
    int bg = t >> 4;        // batch group (2 batches each)
    int vbase = blockIdx.x * 64;
    int b0 = blockIdx.y * 32;

    for (int idx = t; idx < 32*NBETA; idx += 256) sB[idx] = betas[b0*NBETA + idx];
    for (int idx = t; idx < 64*24; idx += 256) {
        int vv = idx / 24, j = idx % 24;
        int v = vbase + vv;
        sW[vv*25 + j] = (v < V_NUM) ? wts[v*24 + j] : 0.0f;
    }
    __syncthreads();

    // --- init v_posed with template + shape blend ---
    float vp[2][4][3];
    float bet[2][NBETA];
#pragma unroll
    for (int bb = 0; bb < 2; bb++)
#pragma unroll
        for (int k = 0; k < NBETA; k++) bet[bb][k] = sB[(bg*2+bb)*NBETA + k];

#pragma unroll
    for (int vv = 0; vv < 4; vv++) {
        int v = vbase + vg*4 + vv;
        if (v < V_NUM) {
            float base0 = vt[v*3+0], base1 = vt[v*3+1], base2 = vt[v*3+2];
            float sdv[30];
#pragma unroll
            for (int i = 0; i < 30; i++) sdv[i] = sd[v*30 + i];
#pragma unroll
            for (int bb = 0; bb < 2; bb++) {
                float a0 = base0, a1 = base1, a2 = base2;
#pragma unroll
                for (int k = 0; k < NBETA; k++) {
                    a0 += sdv[0*10+k] * bet[bb][k];
                    a1 += sdv[1*10+k] * bet[bb][k];
                    a2 += sdv[2*10+k] * bet[bb][k];
                }
                vp[bb][vv][0] = a0; vp[bb][vv][1] = a1; vp[bb][vv][2] = a2;
            }
        } else {
#pragma unroll
            for (int bb = 0; bb < 2; bb++)
                vp[bb][vv][0] = vp[bb][vv][1] = vp[bb][vv][2] = 0.0f;
        }
    }

    // --- phase 1: pose-blend GEMM, K tiled by 8 ---
    float* pd_s = sA;          // [8][192]
    float* pf_s = sA + 1536;   // [8][32]
    for (int kc = 0; kc < KP; kc += 8) {
        __syncthreads();
        int kn = min(8, KP - kc);
        for (int idx = t; idx < 8*192; idx += 256) {
            int kk = idx / 192, c3 = idx % 192;
            int col = vbase*3 + c3;
            pd_s[idx] = (kk < kn && col < VC) ? pdirs[(kc+kk)*VC + col] : 0.0f;
        }
        {
            int kk = t >> 5, bb = t & 31;
            pf_s[t] = (kk < kn) ? g_pfT[(kc+kk)*B_NUM + b0 + bb] : 0.0f;
        }
        __syncthreads();
#pragma unroll
        for (int kk = 0; kk < 8; kk++) {
            float p0 = pf_s[kk*32 + bg*2 + 0];
            float p1 = pf_s[kk*32 + bg*2 + 1];
            float d[12];
            float4 d4;
            d4 = *(const float4*)&pd_s[kk*192 + vg*12 + 0];
            d[0]=d4.x; d[1]=d4.y; d[2]=d4.z; d[3]=d4.w;
            d4 = *(const float4*)&pd_s[kk*192 + vg*12 + 4];
            d[4]=d4.x; d[5]=d4.y; d[6]=d4.z; d[7]=d4.w;
            d4 = *(const float4*)&pd_s[kk*192 + vg*12 + 8];
            d[8]=d4.x; d[9]=d4.y; d[10]=d4.z; d[11]=d4.w;
#pragma unroll
            for (int vv = 0; vv < 4; vv++) {
#pragma unroll
                for (int c = 0; c < 3; c++) {
                    vp[0][vv][c] += p0 * d[vv*3+c];
                    vp[1][vv][c] += p1 * d[vv*3+c];
                }
            }
        }
    }

    __syncthreads();
    // --- load A tile (36KB contiguous copy) ---
    {
        const float4* src = (const float4*)(g_A + b0*288);
        float4* dst = (float4*)sA;
        for (int idx = t; idx < (32*288)/4; idx += 256) dst[idx] = src[idx];
    }
    __syncthreads();

    // --- phase 2: skinning blend ---
    float outv[2][4][3];
#pragma unroll
    for (int bb = 0; bb < 2; bb++)
#pragma unroll
        for (int vv = 0; vv < 4; vv++)
            outv[bb][vv][0] = outv[bb][vv][1] = outv[bb][vv][2] = 0.0f;

#pragma unroll 4
    for (int j = 0; j < 24; j++) {
        float wv[4];
#pragma unroll
        for (int vv = 0; vv < 4; vv++) wv[vv] = sW[(vg*4+vv)*25 + j];
#pragma unroll
        for (int bb = 0; bb < 2; bb++) {
            const float4* Ab = (const float4*)&sA[(bg*2+bb)*288 + j*12];
            float4 a0 = Ab[0], a1 = Ab[1], a2 = Ab[2];
#pragma unroll
            for (int vv = 0; vv < 4; vv++) {
                float x = vp[bb][vv][0], y = vp[bb][vv][1], z = vp[bb][vv][2];
                float q0 = a0.x*x + a0.y*y + a0.z*z + a0.w;
                float q1 = a1.x*x + a1.y*y + a1.z*z + a1.w;
                float q2 = a2.x*x + a2.y*y + a2.z*z + a2.w;
                outv[bb][vv][0] += wv[vv]*q0;
                outv[bb][vv][1] += wv[vv]*q1;
                outv[bb][vv][2] += wv[vv]*q2;
            }
        }
    }

    // --- store ---
#pragma unroll
    for (int bb = 0; bb < 2; bb++) {
        int b = b0 + bg*2 + bb;
        float t0 = trans[b*3+0], t1 = trans[b*3+1], t2 = trans[b*3+2];
#pragma unroll
        for (int vv = 0; vv < 4; vv++) {
            int v = vbase + vg*4 + vv;
            if (v < V_NUM) {
                float* o = out + ((size_t)b*V_NUM + v)*3;
                o[0] = outv[bb][vv][0] + t0;
                o[1] = outv[bb][vv][1] + t1;
                o[2] = outv[bb][vv][2] + t2;
            }
        }
    }
}

extern "C" void kernel_launch(void* const* d_in, const int* in_sizes, int n_in,
                              void* d_out, int out_size)
{
    const float* pose   = (const float*)d_in[0];
    const float* betas  = (const float*)d_in[1];
    const float* trans  = (const float*)d_in[2];
    const float* vt     = (const float*)d_in[3];
    const float* sd     = (const float*)d_in[4];
    const float* pdirs  = (const float*)d_in[5];
    const float* Jreg   = (const float*)d_in[6];
    const float* wts    = (const float*)d_in[7];
    // d_in[8] = parents (fixed SMPL topology, baked into __constant__)

    regress_k<<<24, 128>>>(Jreg, vt, sd);
    pose_k<<<B_NUM, 32>>>(pose, betas);
    dim3 grid((V_NUM + 63)/64, B_NUM/32);
    lbs_k<<<grid, 256>>>(trans, vt, sd, pdirs, wts, betas, (float*)d_out);
}

// round 2
// speedup vs baseline: 1.4118x; 1.4118x over previous
#include <cuda_runtime.h>
#include <math.h>

#define V_NUM 6890
#define B_NUM 512
#define J_NUM 24
#define KP    207   // (J-1)*9
#define NBETA 10
#define VC    (V_NUM*3)   // 20670
#define KT    24          // K-tile for phase-1 GEMM

typedef unsigned long long ull;

__constant__ int c_par[24] = {-1,0,0,0,1,2,3,4,5,6,7,8,9,9,9,12,13,14,16,17,18,19,20,21};

// Scratch (no allocations allowed)
__device__ float g_Jt0[J_NUM*3];
__device__ float g_JS[J_NUM*3*NBETA];
__device__ __align__(16) float g_pfT[KP*B_NUM];          // transposed pose_feature [k][b]
__device__ __align__(16) float g_A[B_NUM*J_NUM*12];      // per-batch joint affines (3x4)

// ---- packed f32x2 helpers (Blackwell FFMA2 path) -------------------------
__device__ __forceinline__ ull pk(float l, float h) {
    ull r; asm("mov.b64 %0, {%1, %2};" : "=l"(r) : "f"(l), "f"(h)); return r;
}
__device__ __forceinline__ float ulo(ull v) {
    float l, h; asm("mov.b64 {%0, %1}, %2;" : "=f"(l), "=f"(h) : "l"(v)); return l;
}
__device__ __forceinline__ float uhi(ull v) {
    float l, h; asm("mov.b64 {%0, %1}, %2;" : "=f"(l), "=f"(h) : "l"(v)); return h;
}
__device__ __forceinline__ ull ffma2(ull a, ull b, ull c) {
    ull r; asm("fma.rn.f32x2 %0, %1, %2, %3;" : "=l"(r) : "l"(a), "l"(b), "l"(c)); return r;
}

// ---------------------------------------------------------------------------
// Kernel 0: zero accumulators (graph-replay safe)
// ---------------------------------------------------------------------------
__global__ void zero_k()
{
    int t = threadIdx.x;
    if (t < J_NUM*3) g_Jt0[t] = 0.0f;
    for (int i = t; i < J_NUM*30; i += 256) g_JS[i] = 0.0f;
}

// ---------------------------------------------------------------------------
// Kernel 1: joint regressor folding, parallel over (j, V-chunk) + atomics.
// ---------------------------------------------------------------------------
__global__ void regress_k(const float* __restrict__ Jreg,
                          const float* __restrict__ vt,
                          const float* __restrict__ sd)
{
    int j = blockIdx.x;
    int chunk = blockIdx.y;                 // 14 chunks
    const int CH = (V_NUM + 13) / 14;       // 493
    int v0 = chunk * CH;
    int v1 = min(v0 + CH, V_NUM);
    int t = threadIdx.x;                    // 256
    int lane = t & 31, w = t >> 5;

    float acc[33];
#pragma unroll
    for (int i = 0; i < 33; i++) acc[i] = 0.f;
    for (int v = v0 + t; v < v1; v += 256) {
        float r = Jreg[j*V_NUM + v];
#pragma unroll
        for (int c = 0; c < 3; c++) acc[c] += r * vt[v*3+c];
#pragma unroll
        for (int i = 0; i < 30; i++) acc[3+i] += r * sd[v*30+i];
    }
    __shared__ float red[8][33];
#pragma unroll
    for (int i = 0; i < 33; i++) {
        float v = acc[i];
#pragma unroll
        for (int o = 16; o; o >>= 1) v += __shfl_xor_sync(0xffffffffu, v, o);
        if (lane == 0) red[w][i] = v;
    }
    __syncthreads();
    if (t < 33) {
        float s = 0.f;
#pragma unroll
        for (int ww = 0; ww < 8; ww++) s += red[ww][t];
        if (t < 3) atomicAdd(&g_Jt0[j*3 + t], s);
        else       atomicAdd(&g_JS[j*30 + (t-3)], s);
    }
}

// ---------------------------------------------------------------------------
// Kernel 2: per-batch: Rodrigues, joints, kinematic chain, pose_feature, A.
// ---------------------------------------------------------------------------
__global__ void pose_k(const float* __restrict__ pose,
                       const float* __restrict__ betas)
{
    int b = blockIdx.x;
    int lane = threadIdx.x;   // 32
    __shared__ float R[24][9];
    __shared__ float Jt[24][3];
    __shared__ float Tl[24][12];
    __shared__ float Tw[24][12];

    if (lane < 24) {
        float rx = pose[b*72 + lane*3 + 0];
        float ry = pose[b*72 + lane*3 + 1];
        float rz = pose[b*72 + lane*3 + 2];
        float ang = sqrtf(rx*rx + ry*ry + rz*rz + 1e-16f);
        float inv = 1.0f/ang;
        float ax = rx*inv, ay = ry*inv, az = rz*inv;
        float s = sinf(ang), c = cosf(ang), tt = 1.0f - c;
        R[lane][0] = c + tt*ax*ax;    R[lane][1] = tt*ax*ay - s*az; R[lane][2] = tt*ax*az + s*ay;
        R[lane][3] = tt*ax*ay + s*az; R[lane][4] = c + tt*ay*ay;    R[lane][5] = tt*ay*az - s*ax;
        R[lane][6] = tt*ax*az - s*ay; R[lane][7] = tt*ay*az + s*ax; R[lane][8] = c + tt*az*az;

        float bet[NBETA];
#pragma unroll
        for (int k = 0; k < NBETA; k++) bet[k] = betas[b*NBETA + k];
#pragma unroll
        for (int c3 = 0; c3 < 3; c3++) {
            float a = g_Jt0[lane*3 + c3];
#pragma unroll
            for (int k = 0; k < NBETA; k++) a += g_JS[lane*30 + c3*10 + k] * bet[k];
            Jt[lane][c3] = a;
        }
    }
    __syncwarp();

    for (int idx = lane; idx < KP; idx += 32) {
        int j = idx/9 + 1, e = idx%9;
        float v = R[j][e] - ((e == 0 || e == 4 || e == 8) ? 1.0f : 0.0f);
        g_pfT[idx*B_NUM + b] = v;
    }

    if (lane < 24) {
        float tx, ty, tz;
        if (lane == 0) { tx = Jt[0][0]; ty = Jt[0][1]; tz = Jt[0][2]; }
        else {
            int p = c_par[lane];
            tx = Jt[lane][0] - Jt[p][0];
            ty = Jt[lane][1] - Jt[p][1];
            tz = Jt[lane][2] - Jt[p][2];
        }
        Tl[lane][0] = R[lane][0]; Tl[lane][1] = R[lane][1]; Tl[lane][2]  = R[lane][2]; Tl[lane][3]  = tx;
        Tl[lane][4] = R[lane][3]; Tl[lane][5] = R[lane][4]; Tl[lane][6]  = R[lane][5]; Tl[lane][7]  = ty;
        Tl[lane][8] = R[lane][6]; Tl[lane][9] = R[lane][7]; Tl[lane][10] = R[lane][8]; Tl[lane][11] = tz;
    }
    __syncwarp();
    if (lane < 12) Tw[0][lane] = Tl[0][lane];
    __syncwarp();
    for (int i = 1; i < 24; i++) {
        if (lane < 12) {
            int r = lane >> 2, cc = lane & 3;
            int p = c_par[i];
            float v = Tw[p][r*4+0]*Tl[i][0+cc] + Tw[p][r*4+1]*Tl[i][4+cc] + Tw[p][r*4+2]*Tl[i][8+cc];
            if (cc == 3) v += Tw[p][r*4+3];
            Tw[i][lane] = v;
        }
        __syncwarp();
    }
    if (lane < 24) {
        float jx = Jt[lane][0], jy = Jt[lane][1], jz = Jt[lane][2];
#pragma unroll
        for (int r = 0; r < 3; r++) {
            float r0 = Tw[lane][r*4+0], r1 = Tw[lane][r*4+1], r2 = Tw[lane][r*4+2];
            float t3 = Tw[lane][r*4+3] - (r0*jx + r1*jy + r2*jz);
            g_A[b*288 + lane*12 + r*4+0] = r0;
            g_A[b*288 + lane*12 + r*4+1] = r1;
            g_A[b*288 + lane*12 + r*4+2] = r2;
            g_A[b*288 + lane*12 + r*4+3] = t3;
        }
    }
}

// ---------------------------------------------------------------------------
// Kernel 3: main fused kernel (packed f32x2).
// Block tile: 32 vertices x 64 batches, 256 threads.
// Thread tile: 4 verts x 2 batches; accumulators packed over vertex pairs.
// ---------------------------------------------------------------------------
#define SMEM_FLOATS (64*288 + 24*32 + 64*NBETA)

__global__ void __launch_bounds__(256, 2) lbs_k(
    const float* __restrict__ trans,
    const float* __restrict__ vt,
    const float* __restrict__ sd,
    const float* __restrict__ pdirs,
    const float* __restrict__ wts,
    const float* __restrict__ betas,
    float* __restrict__ out)
{
    extern __shared__ float smem[];
    float* sA = smem;                    // phase2: [64][288] A tile; phase1 overlays
    float* sW = smem + 64*288;           // [24][32] transposed weights
    float* sB = sW + 24*32;              // [64][NBETA]

    int t = threadIdx.x;
    int vg = t & 7;          // 8 vert-groups of 4 verts
    int bg = t >> 3;         // 32 batch-groups of 2 batches
    int vbase = blockIdx.x * 32;
    int b0 = blockIdx.y * 64;

    for (int idx = t; idx < 64*NBETA; idx += 256) sB[idx] = betas[b0*NBETA + idx];
    for (int idx = t; idx < 24*32; idx += 256) {
        int j = idx >> 5, vv = idx & 31;
        int v = vbase + vv;
        sW[idx] = (v < V_NUM) ? wts[v*24 + j] : 0.0f;
    }
    __syncthreads();

    float bet[2][NBETA];
#pragma unroll
    for (int bb = 0; bb < 2; bb++)
#pragma unroll
        for (int k = 0; k < NBETA; k++) bet[bb][k] = sB[(bg*2+bb)*NBETA + k];

    // --- shape blend init, packed into vert-pair accumulators ---
    ull vp2[2][2][3];   // [bb][pair][c]
#pragma unroll
    for (int p = 0; p < 2; p++) {
        float a[2][2][3];   // [vert-in-pair][bb][c]
#pragma unroll
        for (int q = 0; q < 2; q++) {
            int v = vbase + vg*4 + p*2 + q;
            if (v < V_NUM) {
                float base0 = vt[v*3+0], base1 = vt[v*3+1], base2 = vt[v*3+2];
                float sdv[30];
#pragma unroll
                for (int i = 0; i < 30; i++) sdv[i] = sd[v*30 + i];
#pragma unroll
                for (int bb = 0; bb < 2; bb++) {
                    float a0 = base0, a1 = base1, a2 = base2;
#pragma unroll
                    for (int k = 0; k < NBETA; k++) {
                        a0 += sdv[0*10+k] * bet[bb][k];
                        a1 += sdv[1*10+k] * bet[bb][k];
                        a2 += sdv[2*10+k] * bet[bb][k];
                    }
                    a[q][bb][0] = a0; a[q][bb][1] = a1; a[q][bb][2] = a2;
                }
            } else {
#pragma unroll
                for (int bb = 0; bb < 2; bb++)
                    a[q][bb][0] = a[q][bb][1] = a[q][bb][2] = 0.0f;
            }
        }
#pragma unroll
        for (int bb = 0; bb < 2; bb++)
#pragma unroll
            for (int c = 0; c < 3; c++)
                vp2[bb][p][c] = pk(a[0][bb][c], a[1][bb][c]);
    }

    // --- phase 1: pose-blend GEMM, K tiled by 24, SoA pd tile [k][c][32v] ---
    float* pd_s = sA;            // [KT][3][32] = 2304 floats
    float* pf_s = sA + KT*96;    // [KT][64]   = 1536 floats
    for (int kc = 0; kc < KP; kc += KT) {
        __syncthreads();
        int kn = min(KT, KP - kc);
        for (int idx = t; idx < kn*96; idx += 256) {
            int kk = idx / 96, c3 = idx % 96;
            int col = vbase*3 + c3;
            pd_s[kk*96 + (c3 % 3)*32 + (c3 / 3)] = (col < VC) ? pdirs[(kc+kk)*VC + col] : 0.0f;
        }
        for (int idx = t; idx < KT*64; idx += 256) {
            int kk = idx >> 6, b = idx & 63;
            pf_s[idx] = (kk < kn) ? g_pfT[(kc+kk)*B_NUM + b0 + b] : 0.0f;
        }
        __syncthreads();
#pragma unroll
        for (int kk = 0; kk < KT; kk++) {
            float p0 = pf_s[kk*64 + bg*2 + 0];
            float p1 = pf_s[kk*64 + bg*2 + 1];
            ull pp0 = pk(p0, p0);
            ull pp1 = pk(p1, p1);
#pragma unroll
            for (int c = 0; c < 3; c++) {
                ulonglong2 dd = *(const ulonglong2*)&pd_s[kk*96 + c*32 + vg*4];
                vp2[0][0][c] = ffma2(pp0, dd.x, vp2[0][0][c]);
                vp2[0][1][c] = ffma2(pp0, dd.y, vp2[0][1][c]);
                vp2[1][0][c] = ffma2(pp1, dd.x, vp2[1][0][c]);
                vp2[1][1][c] = ffma2(pp1, dd.y, vp2[1][1][c]);
            }
        }
    }

    __syncthreads();
    // --- load A tile: 64 batches x 288 floats (72KB) ---
    {
        const float4* src = (const float4*)(g_A + b0*288);
        float4* dst = (float4*)sA;
        for (int idx = t; idx < (64*288)/4; idx += 256) dst[idx] = src[idx];
    }
    __syncthreads();

    // --- phase 2: skinning blend, packed over vert pairs ---
    ull o2[2][2][3];
#pragma unroll
    for (int bb = 0; bb < 2; bb++)
#pragma unroll
        for (int p = 0; p < 2; p++)
#pragma unroll
            for (int c = 0; c < 3; c++) o2[bb][p][c] = pk(0.f, 0.f);

#pragma unroll 4
    for (int j = 0; j < 24; j++) {
        ulonglong2 wv = *(const ulonglong2*)&sW[j*32 + vg*4];  // (w_v0,w_v1),(w_v2,w_v3)
#pragma unroll
        for (int bb = 0; bb < 2; bb++) {
            const float4* Ab = (const float4*)&sA[(bg*2+bb)*288 + j*12];
            float4 A0 = Ab[0], A1 = Ab[1], A2 = Ab[2];
            ull r00 = pk(A0.x,A0.x), r01 = pk(A0.y,A0.y), r02 = pk(A0.z,A0.z), t0 = pk(A0.w,A0.w);
            ull r10 = pk(A1.x,A1.x), r11 = pk(A1.y,A1.y), r12 = pk(A1.z,A1.z), t1 = pk(A1.w,A1.w);
            ull r20 = pk(A2.x,A2.x), r21 = pk(A2.y,A2.y), r22 = pk(A2.z,A2.z), t2 = pk(A2.w,A2.w);
#pragma unroll
            for (int p = 0; p < 2; p++) {
                ull x = vp2[bb][p][0], y = vp2[bb][p][1], z = vp2[bb][p][2];
                ull q0 = ffma2(r00, x, ffma2(r01, y, ffma2(r02, z, t0)));
                ull q1 = ffma2(r10, x, ffma2(r11, y, ffma2(r12, z, t1)));
                ull q2 = ffma2(r20, x, ffma2(r21, y, ffma2(r22, z, t2)));
                ull wp = p ? wv.y : wv.x;
                o2[bb][p][0] = ffma2(wp, q0, o2[bb][p][0]);
                o2[bb][p][1] = ffma2(wp, q1, o2[bb][p][1]);
                o2[bb][p][2] = ffma2(wp, q2, o2[bb][p][2]);
            }
        }
    }

    // --- store ---
#pragma unroll
    for (int bb = 0; bb < 2; bb++) {
        int b = b0 + bg*2 + bb;
        float tx = trans[b*3+0], ty = trans[b*3+1], tz = trans[b*3+2];
        float tc[3] = {tx, ty, tz};
#pragma unroll
        for (int p = 0; p < 2; p++) {
            int v0 = vbase + vg*4 + p*2;
#pragma unroll
            for (int c = 0; c < 3; c++) {
                float e0 = ulo(o2[bb][p][c]) + tc[c];
                float e1 = uhi(o2[bb][p][c]) + tc[c];
                if (v0 < V_NUM)     out[((size_t)b*V_NUM + v0)*3 + c] = e0;
                if (v0 + 1 < V_NUM) out[((size_t)b*V_NUM + v0 + 1)*3 + c] = e1;
            }
        }
    }
}

extern "C" void kernel_launch(void* const* d_in, const int* in_sizes, int n_in,
                              void* d_out, int out_size)
{
    const float* pose   = (const float*)d_in[0];
    const float* betas  = (const float*)d_in[1];
    const float* trans  = (const float*)d_in[2];
    const float* vt     = (const float*)d_in[3];
    const float* sd     = (const float*)d_in[4];
    const float* pdirs  = (const float*)d_in[5];
    const float* Jreg   = (const float*)d_in[6];
    const float* wts    = (const float*)d_in[7];
    // d_in[8] = parents (fixed SMPL topology, baked into __constant__)

    static int smem_set = 0;
    if (!smem_set) {
        cudaFuncSetAttribute(lbs_k, cudaFuncAttributeMaxDynamicSharedMemorySize,
                             SMEM_FLOATS * (int)sizeof(float));
        smem_set = 1;
    }

    zero_k<<<1, 256>>>();
    regress_k<<<dim3(24, 14), 256>>>(Jreg, vt, sd);
    pose_k<<<B_NUM, 32>>>(pose, betas);
    dim3 grid((V_NUM + 31)/32, B_NUM/64);
    lbs_k<<<grid, 256, SMEM_FLOATS * (int)sizeof(float)>>>(trans, vt, sd, pdirs, wts, betas, (float*)d_out);
}

// round 3
// speedup vs baseline: 1.8805x; 1.3319x over previous
#include <cuda_runtime.h>
#include <math.h>

#define V_NUM 6890
#define B_NUM 512
#define J_NUM 24
#define KP    207   // (J-1)*9
#define NBETA 10
#define VC    (V_NUM*3)   // 20670
#define KT    23          // 207 = 9 * 23 exactly

typedef unsigned long long ull;

__constant__ int c_par[24] = {-1,0,0,0,1,2,3,4,5,6,7,8,9,9,9,12,13,14,16,17,18,19,20,21};

// Scratch (no allocations allowed)
__device__ float g_Jt0[J_NUM*3];
__device__ float g_JS[J_NUM*3*NBETA];
__device__ __align__(16) float g_pfT[KP*B_NUM];          // transposed pose_feature [k][b]
__device__ __align__(16) float g_A[B_NUM*J_NUM*12];      // per-batch joint affines (3x4)

// ---- packed f32x2 helpers (Blackwell FFMA2 path) -------------------------
__device__ __forceinline__ ull pk(float l, float h) {
    ull r; asm("mov.b64 %0, {%1, %2};" : "=l"(r) : "f"(l), "f"(h)); return r;
}
__device__ __forceinline__ float ulo(ull v) {
    float l, h; asm("mov.b64 {%0, %1}, %2;" : "=f"(l), "=f"(h) : "l"(v)); return l;
}
__device__ __forceinline__ float uhi(ull v) {
    float l, h; asm("mov.b64 {%0, %1}, %2;" : "=f"(l), "=f"(h) : "l"(v)); return h;
}
__device__ __forceinline__ ull ffma2(ull a, ull b, ull c) {
    ull r; asm("fma.rn.f32x2 %0, %1, %2, %3;" : "=l"(r) : "l"(a), "l"(b), "l"(c)); return r;
}

// ---------------------------------------------------------------------------
__global__ void zero_k()
{
    int t = threadIdx.x;
    if (t < J_NUM*3) g_Jt0[t] = 0.0f;
    for (int i = t; i < J_NUM*30; i += 256) g_JS[i] = 0.0f;
}

// ---------------------------------------------------------------------------
__global__ void regress_k(const float* __restrict__ Jreg,
                          const float* __restrict__ vt,
                          const float* __restrict__ sd)
{
    int j = blockIdx.x;
    int chunk = blockIdx.y;                 // 14 chunks
    const int CH = (V_NUM + 13) / 14;       // 493
    int v0 = chunk * CH;
    int v1 = min(v0 + CH, V_NUM);
    int t = threadIdx.x;                    // 256
    int lane = t & 31, w = t >> 5;

    float acc[33];
#pragma unroll
    for (int i = 0; i < 33; i++) acc[i] = 0.f;
    for (int v = v0 + t; v < v1; v += 256) {
        float r = Jreg[j*V_NUM + v];
#pragma unroll
        for (int c = 0; c < 3; c++) acc[c] += r * vt[v*3+c];
#pragma unroll
        for (int i = 0; i < 30; i++) acc[3+i] += r * sd[v*30+i];
    }
    __shared__ float red[8][33];
#pragma unroll
    for (int i = 0; i < 33; i++) {
        float v = acc[i];
#pragma unroll
        for (int o = 16; o; o >>= 1) v += __shfl_xor_sync(0xffffffffu, v, o);
        if (lane == 0) red[w][i] = v;
    }
    __syncthreads();
    if (t < 33) {
        float s = 0.f;
#pragma unroll
        for (int ww = 0; ww < 8; ww++) s += red[ww][t];
        if (t < 3) atomicAdd(&g_Jt0[j*3 + t], s);
        else       atomicAdd(&g_JS[j*30 + (t-3)], s);
    }
}

// ---------------------------------------------------------------------------
__global__ void pose_k(const float* __restrict__ pose,
                       const float* __restrict__ betas)
{
    int b = blockIdx.x;
    int lane = threadIdx.x;   // 32
    __shared__ float R[24][9];
    __shared__ float Jt[24][3];
    __shared__ float Tl[24][12];
    __shared__ float Tw[24][12];

    if (lane < 24) {
        float rx = pose[b*72 + lane*3 + 0];
        float ry = pose[b*72 + lane*3 + 1];
        float rz = pose[b*72 + lane*3 + 2];
        float ang = sqrtf(rx*rx + ry*ry + rz*rz + 1e-16f);
        float inv = 1.0f/ang;
        float ax = rx*inv, ay = ry*inv, az = rz*inv;
        float s = sinf(ang), c = cosf(ang), tt = 1.0f - c;
        R[lane][0] = c + tt*ax*ax;    R[lane][1] = tt*ax*ay - s*az; R[lane][2] = tt*ax*az + s*ay;
        R[lane][3] = tt*ax*ay + s*az; R[lane][4] = c + tt*ay*ay;    R[lane][5] = tt*ay*az - s*ax;
        R[lane][6] = tt*ax*az - s*ay; R[lane][7] = tt*ay*az + s*ax; R[lane][8] = c + tt*az*az;

        float bet[NBETA];
#pragma unroll
        for (int k = 0; k < NBETA; k++) bet[k] = betas[b*NBETA + k];
#pragma unroll
        for (int c3 = 0; c3 < 3; c3++) {
            float a = g_Jt0[lane*3 + c3];
#pragma unroll
            for (int k = 0; k < NBETA; k++) a += g_JS[lane*30 + c3*10 + k] * bet[k];
            Jt[lane][c3] = a;
        }
    }
    __syncwarp();

    for (int idx = lane; idx < KP; idx += 32) {
        int j = idx/9 + 1, e = idx%9;
        float v = R[j][e] - ((e == 0 || e == 4 || e == 8) ? 1.0f : 0.0f);
        g_pfT[idx*B_NUM + b] = v;
    }

    if (lane < 24) {
        float tx, ty, tz;
        if (lane == 0) { tx = Jt[0][0]; ty = Jt[0][1]; tz = Jt[0][2]; }
        else {
            int p = c_par[lane];
            tx = Jt[lane][0] - Jt[p][0];
            ty = Jt[lane][1] - Jt[p][1];
            tz = Jt[lane][2] - Jt[p][2];
        }
        Tl[lane][0] = R[lane][0]; Tl[lane][1] = R[lane][1]; Tl[lane][2]  = R[lane][2]; Tl[lane][3]  = tx;
        Tl[lane][4] = R[lane][3]; Tl[lane][5] = R[lane][4]; Tl[lane][6]  = R[lane][5]; Tl[lane][7]  = ty;
        Tl[lane][8] = R[lane][6]; Tl[lane][9] = R[lane][7]; Tl[lane][10] = R[lane][8]; Tl[lane][11] = tz;
    }
    __syncwarp();
    if (lane < 12) Tw[0][lane] = Tl[0][lane];
    __syncwarp();
    for (int i = 1; i < 24; i++) {
        if (lane < 12) {
            int r = lane >> 2, cc = lane & 3;
            int p = c_par[i];
            float v = Tw[p][r*4+0]*Tl[i][0+cc] + Tw[p][r*4+1]*Tl[i][4+cc] + Tw[p][r*4+2]*Tl[i][8+cc];
            if (cc == 3) v += Tw[p][r*4+3];
            Tw[i][lane] = v;
        }
        __syncwarp();
    }
    if (lane < 24) {
        float jx = Jt[lane][0], jy = Jt[lane][1], jz = Jt[lane][2];
#pragma unroll
        for (int r = 0; r < 3; r++) {
            float r0 = Tw[lane][r*4+0], r1 = Tw[lane][r*4+1], r2 = Tw[lane][r*4+2];
            float t3 = Tw[lane][r*4+3] - (r0*jx + r1*jy + r2*jz);
            g_A[b*288 + lane*12 + r*4+0] = r0;
            g_A[b*288 + lane*12 + r*4+1] = r1;
            g_A[b*288 + lane*12 + r*4+2] = r2;
            g_A[b*288 + lane*12 + r*4+3] = t3;
        }
    }
}

// ---------------------------------------------------------------------------
// Kernel 3: main fused kernel (packed f32x2, 4v x 4b register tile).
// Block tile: 64 vertices x 64 batches, 256 threads.
// ---------------------------------------------------------------------------
#define SMEM_FLOATS (64*288 + 24*64 + 64*NBETA)

__global__ void __launch_bounds__(256, 2) lbs_k(
    const float* __restrict__ trans,
    const float* __restrict__ vt,
    const float* __restrict__ sd,
    const float* __restrict__ pdirs,
    const float* __restrict__ wts,
    const float* __restrict__ betas,
    float* __restrict__ out)
{
    extern __shared__ float smem[];
    float* sA = smem;                    // phase2: [64][288] A tile; phase1 overlays
    float* sW = smem + 64*288;           // [24][64] transposed weights
    float* sB = sW + 24*64;              // [64][NBETA]

    int t = threadIdx.x;
    int vg = t & 15;         // 16 vert-groups of 4 verts
    int bg = t >> 4;         // 16 batch-groups of 4 batches
    int vbase = blockIdx.x * 64;
    int b0 = blockIdx.y * 64;

    for (int idx = t; idx < 64*NBETA; idx += 256) sB[idx] = betas[b0*NBETA + idx];
    for (int idx = t; idx < 24*64; idx += 256) {
        int j = idx >> 6, vv = idx & 63;
        int v = vbase + vv;
        sW[idx] = (v < V_NUM) ? wts[v*24 + j] : 0.0f;
    }
    __syncthreads();

    float bet[4][NBETA];
#pragma unroll
    for (int bb = 0; bb < 4; bb++)
#pragma unroll
        for (int k = 0; k < NBETA; k++) bet[bb][k] = sB[(bg*4+bb)*NBETA + k];

    // --- shape blend init, packed into vert-pair accumulators ---
    ull vp2[4][2][3];   // [bb][pair][c]
#pragma unroll
    for (int p = 0; p < 2; p++) {
        float a[2][4][3];   // [vert-in-pair][bb][c]
#pragma unroll
        for (int q = 0; q < 2; q++) {
            int v = vbase + vg*4 + p*2 + q;
            if (v < V_NUM) {
                float base0 = vt[v*3+0], base1 = vt[v*3+1], base2 = vt[v*3+2];
                float sdv[30];
#pragma unroll
                for (int i = 0; i < 30; i++) sdv[i] = sd[v*30 + i];
#pragma unroll
                for (int bb = 0; bb < 4; bb++) {
                    float a0 = base0, a1 = base1, a2 = base2;
#pragma unroll
                    for (int k = 0; k < NBETA; k++) {
                        a0 += sdv[0*10+k] * bet[bb][k];
                        a1 += sdv[1*10+k] * bet[bb][k];
                        a2 += sdv[2*10+k] * bet[bb][k];
                    }
                    a[q][bb][0] = a0; a[q][bb][1] = a1; a[q][bb][2] = a2;
                }
            } else {
#pragma unroll
                for (int bb = 0; bb < 4; bb++)
                    a[q][bb][0] = a[q][bb][1] = a[q][bb][2] = 0.0f;
            }
        }
#pragma unroll
        for (int bb = 0; bb < 4; bb++)
#pragma unroll
            for (int c = 0; c < 3; c++)
                vp2[bb][p][c] = pk(a[0][bb][c], a[1][bb][c]);
    }

    // --- phase 1: pose-blend GEMM, K tiled by 23 (207 = 9*23) ---
    // pd_s: [KT][3][64] SoA, pf_s: [KT][64]
    float* pd_s = sA;             // KT*192 = 4416 floats
    float* pf_s = sA + KT*192;    // KT*64  = 1472 floats
#pragma unroll 1
    for (int kc = 0; kc < KP; kc += KT) {
        __syncthreads();
        for (int idx = t; idx < KT*192; idx += 256) {
            int kk = idx / 192, c3 = idx % 192;
            int col = vbase*3 + c3;
            pd_s[kk*192 + (c3 % 3)*64 + (c3 / 3)] = (col < VC) ? pdirs[(kc+kk)*VC + col] : 0.0f;
        }
        for (int idx = t; idx < KT*64; idx += 256) {
            int kk = idx >> 6, b = idx & 63;
            pf_s[idx] = g_pfT[(kc+kk)*B_NUM + b0 + b];
        }
        __syncthreads();
#pragma unroll
        for (int kk = 0; kk < KT; kk++) {
            ulonglong2 pf4 = *(const ulonglong2*)&pf_s[kk*64 + bg*4];
            ull pp[4];
            pp[0] = pk(ulo(pf4.x), ulo(pf4.x));
            pp[1] = pk(uhi(pf4.x), uhi(pf4.x));
            pp[2] = pk(ulo(pf4.y), ulo(pf4.y));
            pp[3] = pk(uhi(pf4.y), uhi(pf4.y));
#pragma unroll
            for (int c = 0; c < 3; c++) {
                ulonglong2 dd = *(const ulonglong2*)&pd_s[kk*192 + c*64 + vg*4];
#pragma unroll
                for (int bb = 0; bb < 4; bb++) {
                    vp2[bb][0][c] = ffma2(pp[bb], dd.x, vp2[bb][0][c]);
                    vp2[bb][1][c] = ffma2(pp[bb], dd.y, vp2[bb][1][c]);
                }
            }
        }
    }

    __syncthreads();
    // --- load A tile: 64 batches x 288 floats (72KB) ---
    {
        const float4* src = (const float4*)(g_A + b0*288);
        float4* dst = (float4*)sA;
        for (int idx = t; idx < (64*288)/4; idx += 256) dst[idx] = src[idx];
    }
    __syncthreads();

    // --- phase 2: skinning blend, bb-serial to bound register pressure ---
#pragma unroll 1
    for (int bb = 0; bb < 4; bb++) {
        int b = b0 + bg*4 + bb;
        const float4* Ab = (const float4*)&sA[(bg*4+bb)*288];
        ull o2[2][3];
#pragma unroll
        for (int p = 0; p < 2; p++)
#pragma unroll
            for (int c = 0; c < 3; c++) o2[p][c] = pk(0.f, 0.f);

#pragma unroll 4
        for (int j = 0; j < 24; j++) {
            ulonglong2 wv = *(const ulonglong2*)&sW[j*64 + vg*4];
            float4 A0 = Ab[j*3+0], A1 = Ab[j*3+1], A2 = Ab[j*3+2];
            ull r00 = pk(A0.x,A0.x), r01 = pk(A0.y,A0.y), r02 = pk(A0.z,A0.z), t0 = pk(A0.w,A0.w);
            ull r10 = pk(A1.x,A1.x), r11 = pk(A1.y,A1.y), r12 = pk(A1.z,A1.z), t1 = pk(A1.w,A1.w);
            ull r20 = pk(A2.x,A2.x), r21 = pk(A2.y,A2.y), r22 = pk(A2.z,A2.z), t2 = pk(A2.w,A2.w);
#pragma unroll
            for (int p = 0; p < 2; p++) {
                ull x = vp2[bb][p][0], y = vp2[bb][p][1], z = vp2[bb][p][2];
                ull q0 = ffma2(r00, x, ffma2(r01, y, ffma2(r02, z, t0)));
                ull q1 = ffma2(r10, x, ffma2(r11, y, ffma2(r12, z, t1)));
                ull q2 = ffma2(r20, x, ffma2(r21, y, ffma2(r22, z, t2)));
                ull wp = p ? wv.y : wv.x;
                o2[p][0] = ffma2(wp, q0, o2[p][0]);
                o2[p][1] = ffma2(wp, q1, o2[p][1]);
                o2[p][2] = ffma2(wp, q2, o2[p][2]);
            }
        }

        // store this bb
        float tx = trans[b*3+0], ty = trans[b*3+1], tz = trans[b*3+2];
        float tc[3] = {tx, ty, tz};
#pragma unroll
        for (int p = 0; p < 2; p++) {
            int v0 = vbase + vg*4 + p*2;
#pragma unroll
            for (int c = 0; c < 3; c++) {
                float e0 = ulo(o2[p][c]) + tc[c];
                float e1 = uhi(o2[p][c]) + tc[c];
                if (v0 < V_NUM)     out[((size_t)b*V_NUM + v0)*3 + c] = e0;
                if (v0 + 1 < V_NUM) out[((size_t)b*V_NUM + v0 + 1)*3 + c] = e1;
            }
        }
    }
}

extern "C" void kernel_launch(void* const* d_in, const int* in_sizes, int n_in,
                              void* d_out, int out_size)
{
    const float* pose   = (const float*)d_in[0];
    const float* betas  = (const float*)d_in[1];
    const float* trans  = (const float*)d_in[2];
    const float* vt     = (const float*)d_in[3];
    const float* sd     = (const float*)d_in[4];
    const float* pdirs  = (const float*)d_in[5];
    const float* Jreg   = (const float*)d_in[6];
    const float* wts    = (const float*)d_in[7];
    // d_in[8] = parents (fixed SMPL topology, baked into __constant__)

    static int smem_set = 0;
    if (!smem_set) {
        cudaFuncSetAttribute(lbs_k, cudaFuncAttributeMaxDynamicSharedMemorySize,
                             SMEM_FLOATS * (int)sizeof(float));
        smem_set = 1;
    }

    zero_k<<<1, 256>>>();
    regress_k<<<dim3(24, 14), 256>>>(Jreg, vt, sd);
    pose_k<<<B_NUM, 32>>>(pose, betas);
    dim3 grid((V_NUM + 63)/64, B_NUM/64);
    lbs_k<<<grid, 256, SMEM_FLOATS * (int)sizeof(float)>>>(trans, vt, sd, pdirs, wts, betas, (float*)d_out);
}

// round 5
// speedup vs baseline: 2.1904x; 1.1648x over previous
#include <cuda_runtime.h>
#include <stdint.h>
#include <math.h>

#define V_NUM 6890
#define B_NUM 512
#define J_NUM 24
#define KP    207   // (J-1)*9
#define NBETA 10
#define VC    (V_NUM*3)   // 20670
#define KT    23          // 207 = 9 * 23 exactly
#define NTILE 9
#define BT    128         // batches per block
#define VT    64          // vertices per block

typedef unsigned long long ull;
typedef unsigned int u32;

__constant__ int c_par[24] = {-1,0,0,0,1,2,3,4,5,6,7,8,9,9,9,12,13,14,16,17,18,19,20,21};

// Scratch (no allocations allowed)
__device__ float g_Jt0[J_NUM*3];
__device__ float g_JS[J_NUM*3*NBETA];
__device__ __align__(16) float g_pfT[KP*B_NUM];          // transposed pose_feature [k][b]
__device__ __align__(16) float g_A2[(B_NUM/2)*580];      // batch-pair-interleaved affines, padded rows

// ---- packed f32x2 helpers (Blackwell FFMA2 path) -------------------------
__device__ __forceinline__ ull pk(float l, float h) {
    ull r; asm("mov.b64 %0, {%1, %2};" : "=l"(r) : "f"(l), "f"(h)); return r;
}
__device__ __forceinline__ float ulo(ull v) {
    float l, h; asm("mov.b64 {%0, %1}, %2;" : "=f"(l), "=f"(h) : "l"(v)); return l;
}
__device__ __forceinline__ float uhi(ull v) {
    float l, h; asm("mov.b64 {%0, %1}, %2;" : "=f"(l), "=f"(h) : "l"(v)); return h;
}
__device__ __forceinline__ ull ffma2(ull a, ull b, ull c) {
    ull r; asm("fma.rn.f32x2 %0, %1, %2, %3;" : "=l"(r) : "l"(a), "l"(b), "l"(c)); return r;
}

// ---- cp.async helpers -----------------------------------------------------
__device__ __forceinline__ void cp16(u32 dst, const void* src) {
    asm volatile("cp.async.ca.shared.global [%0], [%1], 16;" :: "r"(dst), "l"(src));
}
__device__ __forceinline__ void cp8(u32 dst, const void* src) {
    asm volatile("cp.async.ca.shared.global [%0], [%1], 8;" :: "r"(dst), "l"(src));
}
__device__ __forceinline__ void cp4(u32 dst, const void* src) {
    asm volatile("cp.async.ca.shared.global [%0], [%1], 4;" :: "r"(dst), "l"(src));
}
__device__ __forceinline__ void cp_commit() { asm volatile("cp.async.commit_group;"); }
template<int N> __device__ __forceinline__ void cp_wait() {
    asm volatile("cp.async.wait_group %0;" :: "n"(N));
}

// ---------------------------------------------------------------------------
__global__ void zero_k()
{
    int t = threadIdx.x;
    if (t < J_NUM*3) g_Jt0[t] = 0.0f;
    for (int i = t; i < J_NUM*30; i += 256) g_JS[i] = 0.0f;
}

// ---------------------------------------------------------------------------
__global__ void regress_k(const float* __restrict__ Jreg,
                          const float* __restrict__ vt,
                          const float* __restrict__ sd)
{
    int j = blockIdx.x;
    int chunk = blockIdx.y;                 // 14 chunks
    const int CH = (V_NUM + 13) / 14;       // 493
    int v0 = chunk * CH;
    int v1 = min(v0 + CH, V_NUM);
    int t = threadIdx.x;                    // 256
    int lane = t & 31, w = t >> 5;

    float acc[33];
#pragma unroll
    for (int i = 0; i < 33; i++) acc[i] = 0.f;
    for (int v = v0 + t; v < v1; v += 256) {
        float r = Jreg[j*V_NUM + v];
#pragma unroll
        for (int c = 0; c < 3; c++) acc[c] += r * vt[v*3+c];
#pragma unroll
        for (int i = 0; i < 30; i++) acc[3+i] += r * sd[v*30+i];
    }
    __shared__ float red[8][33];
#pragma unroll
    for (int i = 0; i < 33; i++) {
        float v = acc[i];
#pragma unroll
        for (int o = 16; o; o >>= 1) v += __shfl_xor_sync(0xffffffffu, v, o);
        if (lane == 0) red[w][i] = v;
    }
    __syncthreads();
    if (t < 33) {
        float s = 0.f;
#pragma unroll
        for (int ww = 0; ww < 8; ww++) s += red[ww][t];
        if (t < 3) atomicAdd(&g_Jt0[j*3 + t], s);
        else       atomicAdd(&g_JS[j*30 + (t-3)], s);
    }
}

// ---------------------------------------------------------------------------
// pose_k: Rodrigues, joints, kinematic chain, pose_feature, A (trans folded,
// batch-pair interleaved into g_A2).
// ---------------------------------------------------------------------------
__global__ void pose_k(const float* __restrict__ pose,
                       const float* __restrict__ betas,
                       const float* __restrict__ trans)
{
    int b = blockIdx.x;
    int lane = threadIdx.x;   // 32
    __shared__ float R[24][9];
    __shared__ float Jt[24][3];
    __shared__ float Tl[24][12];
    __shared__ float Tw[24][12];

    if (lane < 24) {
        float rx = pose[b*72 + lane*3 + 0];
        float ry = pose[b*72 + lane*3 + 1];
        float rz = pose[b*72 + lane*3 + 2];
        float ang = sqrtf(rx*rx + ry*ry + rz*rz + 1e-16f);
        float inv = 1.0f/ang;
        float ax = rx*inv, ay = ry*inv, az = rz*inv;
        float s = sinf(ang), c = cosf(ang), tt = 1.0f - c;
        R[lane][0] = c + tt*ax*ax;    R[lane][1] = tt*ax*ay - s*az; R[lane][2] = tt*ax*az + s*ay;
        R[lane][3] = tt*ax*ay + s*az; R[lane][4] = c + tt*ay*ay;    R[lane][5] = tt*ay*az - s*ax;
        R[lane][6] = tt*ax*az - s*ay; R[lane][7] = tt*ay*az + s*ax; R[lane][8] = c + tt*az*az;

        float bet[NBETA];
#pragma unroll
        for (int k = 0; k < NBETA; k++) bet[k] = betas[b*NBETA + k];
#pragma unroll
        for (int c3 = 0; c3 < 3; c3++) {
            float a = g_Jt0[lane*3 + c3];
#pragma unroll
            for (int k = 0; k < NBETA; k++) a += g_JS[lane*30 + c3*10 + k] * bet[k];
            Jt[lane][c3] = a;
        }
    }
    __syncwarp();

    for (int idx = lane; idx < KP; idx += 32) {
        int j = idx/9 + 1, e = idx%9;
        float v = R[j][e] - ((e == 0 || e == 4 || e == 8) ? 1.0f : 0.0f);
        g_pfT[idx*B_NUM + b] = v;
    }

    if (lane < 24) {
        float tx, ty, tz;
        if (lane == 0) { tx = Jt[0][0]; ty = Jt[0][1]; tz = Jt[0][2]; }
        else {
            int p = c_par[lane];
            tx = Jt[lane][0] - Jt[p][0];
            ty = Jt[lane][1] - Jt[p][1];
            tz = Jt[lane][2] - Jt[p][2];
        }
        Tl[lane][0] = R[lane][0]; Tl[lane][1] = R[lane][1]; Tl[lane][2]  = R[lane][2]; Tl[lane][3]  = tx;
        Tl[lane][4] = R[lane][3]; Tl[lane][5] = R[lane][4]; Tl[lane][6]  = R[lane][5]; Tl[lane][7]  = ty;
        Tl[lane][8] = R[lane][6]; Tl[lane][9] = R[lane][7]; Tl[lane][10] = R[lane][8]; Tl[lane][11] = tz;
    }
    __syncwarp();
    if (lane < 12) Tw[0][lane] = Tl[0][lane];
    __syncwarp();
    for (int i = 1; i < 24; i++) {
        if (lane < 12) {
            int r = lane >> 2, cc = lane & 3;
            int p = c_par[i];
            float v = Tw[p][r*4+0]*Tl[i][0+cc] + Tw[p][r*4+1]*Tl[i][4+cc] + Tw[p][r*4+2]*Tl[i][8+cc];
            if (cc == 3) v += Tw[p][r*4+3];
            Tw[i][lane] = v;
        }
        __syncwarp();
    }
    if (lane < 24) {
        float jx = Jt[lane][0], jy = Jt[lane][1], jz = Jt[lane][2];
        size_t base = (size_t)(b >> 1) * 580 + (b & 1);
#pragma unroll
        for (int r = 0; r < 3; r++) {
            float r0 = Tw[lane][r*4+0], r1 = Tw[lane][r*4+1], r2 = Tw[lane][r*4+2];
            float t3 = Tw[lane][r*4+3] - (r0*jx + r1*jy + r2*jz) + trans[b*3+r];
            int e = lane*12 + r*4;
            g_A2[base + (e+0)*2] = r0;
            g_A2[base + (e+1)*2] = r1;
            g_A2[base + (e+2)*2] = r2;
            g_A2[base + (e+3)*2] = t3;
        }
    }
}

// ---------------------------------------------------------------------------
// Main fused kernel: 512 threads, block tile 64v x 128b, thread tile 4v x 4b.
// cp.async double-buffered K-tiles; A/W/betas prefetched in group 0.
// ---------------------------------------------------------------------------
#define PD_F  (KT*192)          // 4416
#define PF_F  (KT*BT)           // 2944
#define BUF_F (PD_F + PF_F)     // 7360
#define SA2_F (64*580)          // 37120
#define SW_OFF (SA2_F + 2*BUF_F)        // 51840
#define SB_OFF (SW_OFF + 24*64)         // 53376
#define SMEM_F (SB_OFF + BT*NBETA)      // 54656
#define SMEM_BYTES (SMEM_F*4)           // 218624

__global__ void __launch_bounds__(512, 1) lbs_k(
    const float* __restrict__ vt,
    const float* __restrict__ sd,
    const float* __restrict__ pdirs,
    const float* __restrict__ wts,
    const float* __restrict__ betas,
    float* __restrict__ out)
{
    extern __shared__ float smem[];
    u32 sbase = (u32)__cvta_generic_to_shared(smem);

    int t = threadIdx.x;
    int vg = t & 15;          // 16 vert-groups of 4 verts
    int bg = t >> 4;          // 32 batch-groups of 4 batches
    int vbase = blockIdx.x * VT;
    int b0 = blockIdx.y * BT;
    bool tailv = (vbase + VT > V_NUM);

    // ---- group 0: A tile + weights + betas ----
    {
        const float* asrc = g_A2 + (size_t)(b0 >> 1) * 580;
        for (int idx = t; idx < SA2_F/4; idx += 512)
            cp16(sbase + idx*16, asrc + idx*4);
        for (int idx = t; idx < 24*64; idx += 512) {
            int j = idx >> 6, vv = idx & 63;
            int v = vbase + vv;
            cp4(sbase + (SW_OFF + idx)*4, (v < V_NUM) ? &wts[v*24 + j] : wts);
        }
        const float* bsrc = betas + (size_t)b0 * NBETA;
        for (int idx = t; idx < (BT*NBETA)/4; idx += 512)
            cp16(sbase + (SB_OFF)*4 + idx*16, bsrc + idx*4);
    }
    cp_commit();

    // ---- tile fill ----
    auto fill = [&](int buf, int kc) {
        u32 pdst = sbase + (SA2_F + buf*BUF_F)*4;
        const float* psrc = pdirs + (size_t)kc*VC + vbase*3;
        for (int idx = t; idx < PD_F/2; idx += 512) {
            int kk = idx / 96, r = idx - kk*96;
            const float* s = psrc + (size_t)kk*VC + r*2;
            if (tailv && (vbase*3 + r*2 + 2 > VC)) s = pdirs;
            cp8(pdst + (kk*192 + r*2)*4, s);
        }
        u32 fdst = pdst + PD_F*4;
        const float* fsrc = g_pfT + (size_t)kc*B_NUM + b0;
        for (int idx = t; idx < PF_F/4; idx += 512) {
            int kk = idx / 32, r = idx - kk*32;
            cp16(fdst + (kk*BT + r*4)*4, fsrc + (size_t)kk*B_NUM + r*4);
        }
    };

    fill(0, 0);      cp_commit();
    fill(1, KT);     cp_commit();

    ull vp2[4][6];    // [bb][pair of 12-float AoS run]

    int kc = 0;
#pragma unroll 1
    for (int it = 0; it < NTILE; it++, kc += KT) {
        cp_wait<1>();
        __syncthreads();

        if (it == 0) {
            // shape blend init (betas now in smem)
            float f[4][12];
#pragma unroll
            for (int dv = 0; dv < 4; dv++) {
                int v = vbase + vg*4 + dv;
                float vt3[3], sdv[30];
                if (v < V_NUM) {
#pragma unroll
                    for (int c = 0; c < 3; c++) vt3[c] = vt[v*3+c];
#pragma unroll
                    for (int i = 0; i < 30; i++) sdv[i] = sd[v*30+i];
                } else {
#pragma unroll
                    for (int c = 0; c < 3; c++) vt3[c] = 0.f;
#pragma unroll
                    for (int i = 0; i < 30; i++) sdv[i] = 0.f;
                }
#pragma unroll
                for (int bb = 0; bb < 4; bb++) {
                    const float* bp = &smem[SB_OFF + (bg*4+bb)*NBETA];
                    float a0 = vt3[0], a1 = vt3[1], a2 = vt3[2];
#pragma unroll
                    for (int k = 0; k < NBETA; k++) {
                        float be = bp[k];
                        a0 += sdv[k]     * be;
                        a1 += sdv[10+k]  * be;
                        a2 += sdv[20+k]  * be;
                    }
                    f[bb][dv*3+0] = a0; f[bb][dv*3+1] = a1; f[bb][dv*3+2] = a2;
                }
            }
#pragma unroll
            for (int bb = 0; bb < 4; bb++)
#pragma unroll
                for (int e = 0; e < 6; e++)
                    vp2[bb][e] = pk(f[bb][2*e], f[bb][2*e+1]);
        }

        // compute this tile
        const float* pd = smem + SA2_F + (it & 1)*BUF_F;
        const float* pf = pd + PD_F;
#pragma unroll
        for (int kk = 0; kk < KT; kk++) {
            ulonglong2 pf4 = *(const ulonglong2*)&pf[kk*BT + bg*4];
            ull pp[4];
            pp[0] = pk(ulo(pf4.x), ulo(pf4.x));
            pp[1] = pk(uhi(pf4.x), uhi(pf4.x));
            pp[2] = pk(ulo(pf4.y), ulo(pf4.y));
            pp[3] = pk(uhi(pf4.y), uhi(pf4.y));
            const ulonglong2* dp = (const ulonglong2*)&pd[kk*192 + vg*12];
            ulonglong2 d0 = dp[0], d1 = dp[1], d2 = dp[2];
            ull dd[6] = {d0.x, d0.y, d1.x, d1.y, d2.x, d2.y};
#pragma unroll
            for (int bb = 0; bb < 4; bb++)
#pragma unroll
                for (int e = 0; e < 6; e++)
                    vp2[bb][e] = ffma2(pp[bb], dd[e], vp2[bb][e]);
        }

        __syncthreads();
        if (it + 2 < NTILE) fill(it & 1, kc + 2*KT);
        cp_commit();   // possibly empty group (keeps wait numbering uniform)
    }

    // ---- phase 2: skinning blend, batch-pair packed ----
#pragma unroll 1
    for (int p = 0; p < 2; p++) {
        // repack: pairs over (batch 2p, batch 2p+1) per run-element e
        ull xp[12];
        {
            int bl = p*2, bh = p*2+1;
#pragma unroll
            for (int e = 0; e < 12; e++) {
                float fl = (e & 1) ? uhi(vp2[bl][e>>1]) : ulo(vp2[bl][e>>1]);
                float fh = (e & 1) ? uhi(vp2[bh][e>>1]) : ulo(vp2[bh][e>>1]);
                xp[e] = pk(fl, fh);
            }
        }
        ull o2[12];
#pragma unroll
        for (int e = 0; e < 12; e++) o2[e] = pk(0.f, 0.f);

        const float* Abase = &smem[(bg*2 + p)*580];
#pragma unroll 4
        for (int j = 0; j < 24; j++) {
            float4 w4 = *(const float4*)&smem[SW_OFF + j*64 + vg*4];
            ull wp[4] = { pk(w4.x,w4.x), pk(w4.y,w4.y), pk(w4.z,w4.z), pk(w4.w,w4.w) };
            const ulonglong2* Aj = (const ulonglong2*)&Abase[j*24];
            ulonglong2 A0 = Aj[0], A1 = Aj[1], A2 = Aj[2], A3 = Aj[3], A4 = Aj[4], A5 = Aj[5];
            ull a[12] = {A0.x,A0.y,A1.x,A1.y,A2.x,A2.y,A3.x,A3.y,A4.x,A4.y,A5.x,A5.y};
#pragma unroll
            for (int dv = 0; dv < 4; dv++) {
                ull x = xp[dv*3+0], y = xp[dv*3+1], z = xp[dv*3+2];
                ull q0 = ffma2(a[0], x, ffma2(a[1], y, ffma2(a[2],  z, a[3])));
                ull q1 = ffma2(a[4], x, ffma2(a[5], y, ffma2(a[6],  z, a[7])));
                ull q2 = ffma2(a[8], x, ffma2(a[9], y, ffma2(a[10], z, a[11])));
                o2[dv*3+0] = ffma2(wp[dv], q0, o2[dv*3+0]);
                o2[dv*3+1] = ffma2(wp[dv], q1, o2[dv*3+1]);
                o2[dv*3+2] = ffma2(wp[dv], q2, o2[dv*3+2]);
            }
        }

        // store both batches of this pair
        int v0 = vbase + vg*4;
        if (!tailv) {
#pragma unroll
            for (int s = 0; s < 2; s++) {
                int b = b0 + bg*4 + p*2 + s;
                float* o = out + ((size_t)b*V_NUM + v0)*3;
#pragma unroll
                for (int k = 0; k < 6; k++) {
                    float2 v2;
                    v2.x = s ? uhi(o2[2*k])   : ulo(o2[2*k]);
                    v2.y = s ? uhi(o2[2*k+1]) : ulo(o2[2*k+1]);
                    *(float2*)(o + 2*k) = v2;
                }
            }
        } else {
#pragma unroll
            for (int s = 0; s < 2; s++) {
                int b = b0 + bg*4 + p*2 + s;
#pragma unroll
                for (int e = 0; e < 12; e++) {
                    int v = v0 + e/3;
                    if (v < V_NUM) {
                        float val = s ? uhi(o2[e]) : ulo(o2[e]);
                        out[((size_t)b*V_NUM + v)*3 + (e % 3)] = val;
                    }
                }
            }
        }
    }
}

extern "C" void kernel_launch(void* const* d_in, const int* in_sizes, int n_in,
                              void* d_out, int out_size)
{
    const float* pose   = (const float*)d_in[0];
    const float* betas  = (const float*)d_in[1];
    const float* trans  = (const float*)d_in[2];
    const float* vt     = (const float*)d_in[3];
    const float* sd     = (const float*)d_in[4];
    const float* pdirs  = (const float*)d_in[5];
    const float* Jreg   = (const float*)d_in[6];
    const float* wts    = (const float*)d_in[7];
    // d_in[8] = parents (fixed SMPL topology, baked into __constant__)

    static int smem_set = 0;
    if (!smem_set) {
        cudaFuncSetAttribute(lbs_k, cudaFuncAttributeMaxDynamicSharedMemorySize,
                             SMEM_BYTES);
        smem_set = 1;
    }

    zero_k<<<1, 256>>>();
    regress_k<<<dim3(24, 14), 256>>>(Jreg, vt, sd);
    pose_k<<<B_NUM, 32>>>(pose, betas, trans);
    dim3 grid((V_NUM + VT - 1)/VT, B_NUM/BT);   // 108 x 4
    lbs_k<<<grid, 512, SMEM_BYTES>>>(vt, sd, pdirs, wts, betas, (float*)d_out);
}